// round 1
// baseline (speedup 1.0000x reference)
#include <cuda_runtime.h>

#define NEG_SLOPE 0.2f
#define BN_EPS_F  1e-5f

static constexpr int NMAX = 100000;

// ---------------- scratch (static device globals; no allocation) ----------------
__device__ float g_h1  [(size_t)NMAX * 128];
__device__ float g_agg1[(size_t)NMAX * 128];
__device__ float g_h2  [(size_t)NMAX * 80];
__device__ float g_agg2[(size_t)NMAX * 80];
__device__ float g_as1 [NMAX * 2];
__device__ float g_ad1 [NMAX * 2];
__device__ float g_den1[NMAX * 2];
__device__ float g_as2 [NMAX * 2];
__device__ float g_ad2 [NMAX * 2];
__device__ float g_den2[NMAX * 2];
__device__ float g_colsum[128];
__device__ float g_colsq [128];
__device__ float g_scale [128];
__device__ float g_shift [128];

// ---------------- vector global reductions (sm_90+) ----------------
__device__ __forceinline__ void red_add_v4(float* addr, float a, float b, float c, float d) {
    asm volatile("red.global.add.v4.f32 [%0], {%1, %2, %3, %4};"
                 :: "l"(addr), "f"(a), "f"(b), "f"(c), "f"(d) : "memory");
}

// ---------------- GEMM: H[n,NOUT] = X[n,128] @ W[128,NOUT]  (optional BN on X) ----
template<int NOUT>
__global__ __launch_bounds__(256, 2)
void gemm_k(const float* __restrict__ X, const float* __restrict__ W,
            float* __restrict__ H, int n,
            const float* __restrict__ scale, const float* __restrict__ shift)
{
    constexpr int TN = NOUT / 16;            // 8 for 128, 5 for 80
    extern __shared__ float smem[];
    float* sW = smem;                        // [128 * NOUT]
    float* sX = smem + 128 * NOUT;           // [64 * 132] (padded)

    const int tid = threadIdx.x;
    const int tx  = tid & 15;
    const int ty  = tid >> 4;
    const int row0 = blockIdx.x * 64;

    for (int i = tid; i < 128 * NOUT; i += 256) sW[i] = W[i];
    const bool bn = (scale != nullptr);
    for (int i = tid; i < 64 * 128; i += 256) {
        int r = i >> 7, c = i & 127;
        int gr = row0 + r;
        float v = (gr < n) ? X[(size_t)gr * 128 + c] : 0.0f;
        if (bn) v = fmaf(v, scale[c], shift[c]);
        sX[r * 132 + c] = v;
    }
    __syncthreads();

    float acc[4][TN];
    #pragma unroll
    for (int i = 0; i < 4; i++)
        #pragma unroll
        for (int j = 0; j < TN; j++) acc[i][j] = 0.0f;

    #pragma unroll 8
    for (int k = 0; k < 128; k++) {
        float a[4];
        #pragma unroll
        for (int i = 0; i < 4; i++) a[i] = sX[(ty * 4 + i) * 132 + k];
        float b[TN];
        if constexpr (TN == 8) {
            const float4* bp = reinterpret_cast<const float4*>(sW + k * NOUT + tx * 8);
            float4 b0 = bp[0], b1 = bp[1];
            b[0]=b0.x; b[1]=b0.y; b[2]=b0.z; b[3]=b0.w;
            b[4]=b1.x; b[5]=b1.y; b[6]=b1.z; b[7]=b1.w;
        } else {
            #pragma unroll
            for (int j = 0; j < TN; j++) b[j] = sW[k * NOUT + tx * TN + j];
        }
        #pragma unroll
        for (int i = 0; i < 4; i++)
            #pragma unroll
            for (int j = 0; j < TN; j++) acc[i][j] = fmaf(a[i], b[j], acc[i][j]);
    }

    #pragma unroll
    for (int i = 0; i < 4; i++) {
        int gr = row0 + ty * 4 + i;
        if (gr < n) {
            #pragma unroll
            for (int j = 0; j < TN; j++)
                H[(size_t)gr * NOUT + tx * TN + j] = acc[i][j];
        }
    }
}

// ---- per-node: a_src/a_dst dot products + self-loop init of den/agg (warp/node) ----
template<int NOUT>
__global__ void att_self_k(const float* __restrict__ H, const float* __restrict__ attS,
                           const float* __restrict__ attD, float* __restrict__ AS,
                           float* __restrict__ AD, float* __restrict__ DEN,
                           float* __restrict__ AGG, int n)
{
    constexpr int C = NOUT / 2;
    const int lane = threadIdx.x & 31;
    const int i = (blockIdx.x * blockDim.x + threadIdx.x) >> 5;
    if (i >= n) return;
    const float* row = H + (size_t)i * NOUT;

    float s0 = 0.f, s1 = 0.f, d0 = 0.f, d1 = 0.f;
    for (int c = lane; c < NOUT; c += 32) {
        float v = row[c];
        float p = v * attS[c];
        float q = v * attD[c];
        if (c < C) { s0 += p; d0 += q; } else { s1 += p; d1 += q; }
    }
    #pragma unroll
    for (int o = 16; o > 0; o >>= 1) {
        s0 += __shfl_xor_sync(0xffffffffu, s0, o);
        s1 += __shfl_xor_sync(0xffffffffu, s1, o);
        d0 += __shfl_xor_sync(0xffffffffu, d0, o);
        d1 += __shfl_xor_sync(0xffffffffu, d1, o);
    }
    float a0 = s0 + d0; a0 = a0 > 0.f ? a0 : NEG_SLOPE * a0;
    float a1 = s1 + d1; a1 = a1 > 0.f ? a1 : NEG_SLOPE * a1;
    float e0 = __expf(a0), e1 = __expf(a1);
    if (lane == 0) {
        AS[i * 2] = s0;  AS[i * 2 + 1] = s1;
        AD[i * 2] = d0;  AD[i * 2 + 1] = d1;
        DEN[i * 2] = e0; DEN[i * 2 + 1] = e1;
    }
    for (int c = lane; c < NOUT; c += 32)
        AGG[(size_t)i * NOUT + c] = row[c] * (c < C ? e0 : e1);
}

// ---- edge scatter: warp per edge, red.v4 into AGG[dst], scalar red into DEN[dst] ----
template<int NOUT>
__global__ void edge_k(const int* __restrict__ src, const int* __restrict__ dst,
                       const float* __restrict__ AS, const float* __restrict__ AD,
                       const float* __restrict__ H, float* __restrict__ AGG,
                       float* __restrict__ DEN, int E)
{
    constexpr int C = NOUT / 2;
    const int lane = threadIdx.x & 31;
    const int e = (blockIdx.x * blockDim.x + threadIdx.x) >> 5;
    if (e >= E) return;
    if (lane * 4 >= NOUT) return;                 // NOUT=80: lanes 20..31 idle

    const int s = __ldg(src + e);
    const int d = __ldg(dst + e);
    const int h = (lane * 4 >= C) ? 1 : 0;        // this lane's head
    float aa = __ldg(AS + s * 2 + h) + __ldg(AD + d * 2 + h);
    aa = aa > 0.f ? aa : NEG_SLOPE * aa;
    float w = __expf(aa);
    if (lane == 0 || lane == C / 4) atomicAdd(DEN + d * 2 + h, w);
    float4 v = *reinterpret_cast<const float4*>(H + (size_t)s * NOUT + lane * 4);
    red_add_v4(AGG + (size_t)d * NOUT + lane * 4, v.x * w, v.y * w, v.z * w, v.w * w);
}

// ---- zero BN accumulators ----
__global__ void zero_k(float* a, float* b) {
    a[threadIdx.x] = 0.f; b[threadIdx.x] = 0.f;
}

// ---- layer-1 finalize (agg/den + bias) in place + per-column sum/sumsq ----
__global__ void fin_bn_k(float* __restrict__ AGG, const float* __restrict__ DEN,
                         const float* __restrict__ b1, float* __restrict__ colsum,
                         float* __restrict__ colsq, int n)
{
    const int t = threadIdx.x;        // 128 threads: one column each
    const int r0 = blockIdx.x * 128;
    const int r1 = min(r0 + 128, n);
    const float bias = b1[t];
    const int hsel = t >> 6;
    float sum = 0.f, sq = 0.f;
    for (int r = r0; r < r1; r++) {
        float den = DEN[r * 2 + hsel];
        float v = AGG[(size_t)r * 128 + t] / den + bias;
        AGG[(size_t)r * 128 + t] = v;
        sum += v; sq += v * v;
    }
    atomicAdd(&colsum[t], sum);
    atomicAdd(&colsq[t], sq);
}

// ---- fold mean/var + gamma/beta into per-column scale/shift ----
__global__ void bnstat_k(const float* __restrict__ colsum, const float* __restrict__ colsq,
                         const float* __restrict__ gamma, const float* __restrict__ beta,
                         float* __restrict__ scale, float* __restrict__ shift, int n)
{
    const int t = threadIdx.x;
    float inv_n = 1.0f / (float)n;
    float mean = colsum[t] * inv_n;
    float var  = colsq[t] * inv_n - mean * mean;
    float sc   = gamma[t] * rsqrtf(var + BN_EPS_F);
    scale[t] = sc;
    shift[t] = beta[t] - mean * sc;
}

// ---- layer-2 finalize: head-mean + bias + log_softmax over 40 classes (warp/node) ----
__global__ void final_k(const float* __restrict__ AGG2, const float* __restrict__ DEN2,
                        const float* __restrict__ b2, float* __restrict__ out, int n)
{
    const int lane = threadIdx.x & 31;
    const int i = (blockIdx.x * blockDim.x + threadIdx.x) >> 5;
    if (i >= n) return;
    const float id0 = 1.0f / DEN2[i * 2];
    const float id1 = 1.0f / DEN2[i * 2 + 1];
    const float* row = AGG2 + (size_t)i * 80;

    float v0 = 0.5f * (row[lane] * id0 + row[40 + lane] * id1) + b2[lane];       // c = lane (<32)
    float v1 = -1e30f;
    if (lane < 8)
        v1 = 0.5f * (row[lane + 32] * id0 + row[72 + lane] * id1) + b2[lane + 32]; // c = lane+32

    float m = fmaxf(v0, v1);
    #pragma unroll
    for (int o = 16; o > 0; o >>= 1) m = fmaxf(m, __shfl_xor_sync(0xffffffffu, m, o));
    float ssum = __expf(v0 - m) + (lane < 8 ? __expf(v1 - m) : 0.f);
    #pragma unroll
    for (int o = 16; o > 0; o >>= 1) ssum += __shfl_xor_sync(0xffffffffu, ssum, o);
    float lse = m + __logf(ssum);

    out[(size_t)i * 40 + lane] = v0 - lse;
    if (lane < 8) out[(size_t)i * 40 + lane + 32] = v1 - lse;
}

// ------------------------------- launcher -------------------------------
extern "C" void kernel_launch(void* const* d_in, const int* in_sizes, int n_in,
                              void* d_out, int out_size)
{
    const float* x      = (const float*)d_in[0];
    const int*   ei     = (const int*)  d_in[1];
    const float* W1     = (const float*)d_in[2];
    const float* att_s1 = (const float*)d_in[3];
    const float* att_d1 = (const float*)d_in[4];
    const float* b1     = (const float*)d_in[5];
    const float* gamma  = (const float*)d_in[6];
    const float* beta   = (const float*)d_in[7];
    const float* W2     = (const float*)d_in[8];
    const float* att_s2 = (const float*)d_in[9];
    const float* att_d2 = (const float*)d_in[10];
    const float* b2     = (const float*)d_in[11];
    float* out = (float*)d_out;

    const int n = in_sizes[0] / 128;
    const int E = in_sizes[1] / 2;
    const int* src = ei;
    const int* dst = ei + E;

    float *h1, *agg1, *h2, *agg2, *as1, *ad1, *den1, *as2, *ad2, *den2;
    float *colsum, *colsq, *scale, *shift;
    cudaGetSymbolAddress((void**)&h1,   g_h1);
    cudaGetSymbolAddress((void**)&agg1, g_agg1);
    cudaGetSymbolAddress((void**)&h2,   g_h2);
    cudaGetSymbolAddress((void**)&agg2, g_agg2);
    cudaGetSymbolAddress((void**)&as1,  g_as1);
    cudaGetSymbolAddress((void**)&ad1,  g_ad1);
    cudaGetSymbolAddress((void**)&den1, g_den1);
    cudaGetSymbolAddress((void**)&as2,  g_as2);
    cudaGetSymbolAddress((void**)&ad2,  g_ad2);
    cudaGetSymbolAddress((void**)&den2, g_den2);
    cudaGetSymbolAddress((void**)&colsum, g_colsum);
    cudaGetSymbolAddress((void**)&colsq,  g_colsq);
    cudaGetSymbolAddress((void**)&scale,  g_scale);
    cudaGetSymbolAddress((void**)&shift,  g_shift);

    const size_t smem1 = (128 * 128 + 64 * 132) * sizeof(float);  // 99328 B
    const size_t smem2 = (128 * 80  + 64 * 132) * sizeof(float);  // 74752 B
    cudaFuncSetAttribute((const void*)gemm_k<128>, cudaFuncAttributeMaxDynamicSharedMemorySize, (int)smem1);
    cudaFuncSetAttribute((const void*)gemm_k<80>,  cudaFuncAttributeMaxDynamicSharedMemorySize, (int)smem2);

    const int gb = (n + 63) / 64;     // gemm blocks
    const int wb = (n + 7) / 8;       // warp-per-node blocks (256 thr)
    const int eb = (E + 7) / 8;       // warp-per-edge blocks (256 thr)

    // ---- layer 1 ----
    gemm_k<128><<<gb, 256, smem1>>>(x, W1, h1, n, nullptr, nullptr);
    att_self_k<128><<<wb, 256>>>(h1, att_s1, att_d1, as1, ad1, den1, agg1, n);
    edge_k<128><<<eb, 256>>>(src, dst, as1, ad1, h1, agg1, den1, E);

    // ---- batchnorm ----
    zero_k<<<1, 128>>>(colsum, colsq);
    fin_bn_k<<<(n + 127) / 128, 128>>>(agg1, den1, b1, colsum, colsq, n);
    bnstat_k<<<1, 128>>>(colsum, colsq, gamma, beta, scale, shift, n);

    // ---- layer 2 (BN folded into GEMM A-load) ----
    gemm_k<80><<<gb, 256, smem2>>>(agg1, W2, h2, n, scale, shift);
    att_self_k<80><<<wb, 256>>>(h2, att_s2, att_d2, as2, ad2, den2, agg2, n);
    edge_k<80><<<eb, 256>>>(src, dst, as2, ad2, h2, agg2, den2, E);

    // ---- head mean + bias + log_softmax ----
    final_k<<<wb, 256>>>(agg2, den2, b2, out, n);
}

// round 3
// speedup vs baseline: 1.6838x; 1.6838x over previous
#include <cuda_runtime.h>

#define NEG_SLOPE 0.2f
#define BN_EPS_F  1e-5f

static constexpr int NMAX = 100000;
static constexpr int EMAX = 1700000;

// ---------------- scratch (static device globals; no allocation) ----------------
__device__ float  g_h1  [(size_t)NMAX * 128];
__device__ float  g_agg1[(size_t)NMAX * 128];
__device__ float  g_h2  [(size_t)NMAX * 80];
__device__ float2 g_as1 [NMAX];
__device__ float2 g_ad1 [NMAX];
__device__ float2 g_as2 [NMAX];
__device__ float2 g_ad2 [NMAX];
__device__ int    g_deg   [NMAX];
__device__ int    g_incl  [NMAX];
__device__ int    g_rowptr[NMAX + 1];
__device__ int    g_cursor[NMAX];
__device__ int    g_col   [EMAX];
__device__ int    g_bsum  [256];
__device__ float  g_colsum[128];
__device__ float  g_colsq [128];
__device__ float  g_scale [128];
__device__ float  g_shift [128];

// ---------------- CSR build ----------------
__global__ void zero_init_k(int* deg, float* colsum, float* colsq, int n) {
    int i = blockIdx.x * blockDim.x + threadIdx.x;
    if (i < n) deg[i] = 0;
    if (i < 128) { colsum[i] = 0.f; colsq[i] = 0.f; }
}

__global__ void hist_k(const int* __restrict__ dst, int* __restrict__ deg, int E) {
    int e = blockIdx.x * blockDim.x + threadIdx.x;
    if (e < E) atomicAdd(&deg[dst[e]], 1);
}

// per-block (1024) inclusive scan + block sums
__global__ void scan1_k(const int* __restrict__ deg, int* __restrict__ incl,
                        int* __restrict__ bsum, int n) {
    __shared__ int wsum[32];
    const int tid = threadIdx.x;
    const int gid = blockIdx.x * 1024 + tid;
    const int lane = tid & 31, w = tid >> 5;
    int x = (gid < n) ? deg[gid] : 0;
    #pragma unroll
    for (int o = 1; o < 32; o <<= 1) {
        int t = __shfl_up_sync(0xffffffffu, x, o);
        if (lane >= o) x += t;
    }
    if (lane == 31) wsum[w] = x;
    __syncthreads();
    if (w == 0) {
        int y = wsum[lane];
        #pragma unroll
        for (int o = 1; o < 32; o <<= 1) {
            int t = __shfl_up_sync(0xffffffffu, y, o);
            if (lane >= o) y += t;
        }
        wsum[lane] = y;
    }
    __syncthreads();
    if (w > 0) x += wsum[w - 1];
    if (gid < n) incl[gid] = x;
    if (tid == 1023) bsum[blockIdx.x] = x;
}

// exclusive scan of block sums (tiny; serial in one thread)
__global__ void scan2_k(int* bsum, int nb) {
    if (threadIdx.x == 0) {
        int run = 0;
        for (int b = 0; b < nb; b++) { int t = bsum[b]; bsum[b] = run; run += t; }
    }
}

// rowptr (exclusive, length n+1) + cursor
__global__ void scan3_k(const int* __restrict__ incl, const int* __restrict__ bsum,
                        const int* __restrict__ deg, int* __restrict__ rowptr,
                        int* __restrict__ cursor, int n) {
    int i = blockIdx.x * blockDim.x + threadIdx.x;
    if (i < n) {
        int v = incl[i] + bsum[i >> 10];
        rowptr[i + 1] = v;
        cursor[i] = v - deg[i];
    }
    if (i == 0) rowptr[0] = 0;
}

__global__ void fill_k(const int* __restrict__ src, const int* __restrict__ dst,
                       int* __restrict__ cursor, int* __restrict__ col, int E) {
    int e = blockIdx.x * blockDim.x + threadIdx.x;
    if (e < E) {
        int p = atomicAdd(&cursor[dst[e]], 1);
        col[p] = src[e];
    }
}

// ---- GEMM: H[n,NOUT] = X[n,128] @ W[128,NOUT], optional BN fold on X,
//      fused epilogue: AS[i]/AD[i] attention dot-products (per head) ----
template<int NOUT>
__global__ __launch_bounds__(256, 2)
void gemm_k(const float* __restrict__ X, const float* __restrict__ W,
            float* __restrict__ H, int n,
            const float* __restrict__ scale, const float* __restrict__ shift,
            const float* __restrict__ attS, const float* __restrict__ attD,
            float2* __restrict__ AS, float2* __restrict__ AD)
{
    constexpr int TN = NOUT / 16;            // 8 for 128, 5 for 80
    extern __shared__ float smem[];
    float* sW = smem;                        // [128 * NOUT]
    float* sX = smem + 128 * NOUT;           // [64 * 132]

    const int tid = threadIdx.x;
    const int tx  = tid & 15;
    const int ty  = tid >> 4;
    const int row0 = blockIdx.x * 64;

    for (int i = tid; i < 128 * NOUT; i += 256) sW[i] = W[i];
    const bool bn = (scale != nullptr);
    for (int i = tid; i < 64 * 128; i += 256) {
        int r = i >> 7, c = i & 127;
        int gr = row0 + r;
        float v = (gr < n) ? X[(size_t)gr * 128 + c] : 0.0f;
        if (bn) v = fmaf(v, scale[c], shift[c]);
        sX[r * 132 + c] = v;
    }
    __syncthreads();

    float acc[4][TN];
    #pragma unroll
    for (int i = 0; i < 4; i++)
        #pragma unroll
        for (int j = 0; j < TN; j++) acc[i][j] = 0.0f;

    #pragma unroll 8
    for (int k = 0; k < 128; k++) {
        float a[4];
        #pragma unroll
        for (int i = 0; i < 4; i++) a[i] = sX[(ty * 4 + i) * 132 + k];
        float b[TN];
        if constexpr (TN == 8) {
            const float4* bp = reinterpret_cast<const float4*>(sW + k * NOUT + tx * 8);
            float4 b0 = bp[0], b1 = bp[1];
            b[0]=b0.x; b[1]=b0.y; b[2]=b0.z; b[3]=b0.w;
            b[4]=b1.x; b[5]=b1.y; b[6]=b1.z; b[7]=b1.w;
        } else {
            #pragma unroll
            for (int j = 0; j < TN; j++) b[j] = sW[k * NOUT + tx * TN + j];
        }
        #pragma unroll
        for (int i = 0; i < 4; i++)
            #pragma unroll
            for (int j = 0; j < TN; j++) acc[i][j] = fmaf(a[i], b[j], acc[i][j]);
    }

    // store H
    #pragma unroll
    for (int i = 0; i < 4; i++) {
        int gr = row0 + ty * 4 + i;
        if (gr < n) {
            #pragma unroll
            for (int j = 0; j < TN; j++)
                H[(size_t)gr * NOUT + tx * TN + j] = acc[i][j];
        }
    }

    // fused attention dot products: per row, per head
    float av[TN], dv[TN];
    #pragma unroll
    for (int j = 0; j < TN; j++) {
        av[j] = attS[tx * TN + j];
        dv[j] = attD[tx * TN + j];
    }
    #pragma unroll
    for (int i = 0; i < 4; i++) {
        float ps = 0.f, pd = 0.f;
        #pragma unroll
        for (int j = 0; j < TN; j++) {
            ps = fmaf(acc[i][j], av[j], ps);
            pd = fmaf(acc[i][j], dv[j], pd);
        }
        #pragma unroll
        for (int o = 1; o < 8; o <<= 1) {
            ps += __shfl_xor_sync(0xffffffffu, ps, o);
            pd += __shfl_xor_sync(0xffffffffu, pd, o);
        }
        float ps8 = __shfl_xor_sync(0xffffffffu, ps, 8);
        float pd8 = __shfl_xor_sync(0xffffffffu, pd, 8);
        int gr = row0 + ty * 4 + i;
        if (tx == 0 && gr < n) {
            AS[gr] = make_float2(ps, ps8);   // (head0, head1)
            AD[gr] = make_float2(pd, pd8);
        }
    }
}

// ---- layer-1 gather: warp per dst node; CSR neighbors + self loop.
//      out = (sum_e w_e * h[src_e] + w_self * h[i]) / den + b1 ----
__global__ __launch_bounds__(256)
void gather1_k(const int* __restrict__ rowptr, const int* __restrict__ col,
               const float2* __restrict__ AS, const float2* __restrict__ AD,
               const float* __restrict__ H, const float* __restrict__ b1,
               float* __restrict__ OUT, int n)
{
    const int lane = threadIdx.x & 31;
    const int i = (blockIdx.x * blockDim.x + threadIdx.x) >> 5;
    if (i >= n) return;
    const bool h1sel = lane >= 16;            // lane*4 >= 64
    const float2 adv = AD[i];
    const float ad = h1sel ? adv.y : adv.x;

    float4 acc = make_float4(0.f, 0.f, 0.f, 0.f);
    float den = 0.f;
    const int beg = rowptr[i], end = rowptr[i + 1];
    #pragma unroll 4
    for (int e = beg; e < end; e++) {
        const int s = __ldg(col + e);
        const float2 asv = __ldg(AS + s);
        float a = (h1sel ? asv.y : asv.x) + ad;
        a = a > 0.f ? a : NEG_SLOPE * a;
        const float w = __expf(a);
        den += w;
        const float4 v = *reinterpret_cast<const float4*>(H + (size_t)s * 128 + lane * 4);
        acc.x = fmaf(w, v.x, acc.x); acc.y = fmaf(w, v.y, acc.y);
        acc.z = fmaf(w, v.z, acc.z); acc.w = fmaf(w, v.w, acc.w);
    }
    // self loop
    {
        const float2 asv = AS[i];
        float a = (h1sel ? asv.y : asv.x) + ad;
        a = a > 0.f ? a : NEG_SLOPE * a;
        const float w = __expf(a);
        den += w;
        const float4 v = *reinterpret_cast<const float4*>(H + (size_t)i * 128 + lane * 4);
        acc.x = fmaf(w, v.x, acc.x); acc.y = fmaf(w, v.y, acc.y);
        acc.z = fmaf(w, v.z, acc.z); acc.w = fmaf(w, v.w, acc.w);
    }
    const float inv = 1.0f / den;
    const float4 bv = *reinterpret_cast<const float4*>(b1 + lane * 4);
    float4 o;
    o.x = acc.x * inv + bv.x; o.y = acc.y * inv + bv.y;
    o.z = acc.z * inv + bv.z; o.w = acc.w * inv + bv.w;
    *reinterpret_cast<float4*>(OUT + (size_t)i * 128 + lane * 4) = o;
}

// ---- per-column sum / sumsq over agg1 ----
__global__ void bnstats_k(const float* __restrict__ A, float* __restrict__ colsum,
                          float* __restrict__ colsq, int n)
{
    const int c = threadIdx.x;                 // 128 threads
    const int r0 = blockIdx.x * 256;
    const int r1 = min(r0 + 256, n);
    float s = 0.f, q = 0.f;
    for (int r = r0; r < r1; r++) {
        float v = A[(size_t)r * 128 + c];
        s += v; q = fmaf(v, v, q);
    }
    atomicAdd(&colsum[c], s);
    atomicAdd(&colsq[c], q);
}

__global__ void bnfold_k(const float* __restrict__ colsum, const float* __restrict__ colsq,
                         const float* __restrict__ gamma, const float* __restrict__ beta,
                         float* __restrict__ scale, float* __restrict__ shift, int n)
{
    const int t = threadIdx.x;
    float inv_n = 1.0f / (float)n;
    float mean = colsum[t] * inv_n;
    float var  = colsq[t] * inv_n - mean * mean;
    float sc   = gamma[t] * rsqrtf(var + BN_EPS_F);
    scale[t] = sc;
    shift[t] = beta[t] - mean * sc;
}

// ---- layer-2 gather + head-mean + bias + log_softmax, writes out directly ----
__global__ __launch_bounds__(256)
void gather2_k(const int* __restrict__ rowptr, const int* __restrict__ col,
               const float2* __restrict__ AS, const float2* __restrict__ AD,
               const float* __restrict__ H, const float* __restrict__ b2,
               float* __restrict__ out, int n)
{
    const int lane = threadIdx.x & 31;
    const int i = (blockIdx.x * blockDim.x + threadIdx.x) >> 5;
    if (i >= n) return;
    const bool act = lane < 20;               // lane*4 < 80
    const bool h1sel = lane >= 10;            // lane*4 >= 40
    const float2 adv = AD[i];
    const float ad = h1sel ? adv.y : adv.x;

    float4 acc = make_float4(0.f, 0.f, 0.f, 0.f);
    float den = 0.f;
    const int beg = rowptr[i], end = rowptr[i + 1];
    #pragma unroll 4
    for (int e = beg; e < end; e++) {
        const int s = __ldg(col + e);
        const float2 asv = __ldg(AS + s);
        float a = (h1sel ? asv.y : asv.x) + ad;
        a = a > 0.f ? a : NEG_SLOPE * a;
        const float w = __expf(a);
        den += w;
        if (act) {
            const float4 v = *reinterpret_cast<const float4*>(H + (size_t)s * 80 + lane * 4);
            acc.x = fmaf(w, v.x, acc.x); acc.y = fmaf(w, v.y, acc.y);
            acc.z = fmaf(w, v.z, acc.z); acc.w = fmaf(w, v.w, acc.w);
        }
    }
    // self loop
    {
        const float2 asv = AS[i];
        float a = (h1sel ? asv.y : asv.x) + ad;
        a = a > 0.f ? a : NEG_SLOPE * a;
        const float w = __expf(a);
        den += w;
        if (act) {
            const float4 v = *reinterpret_cast<const float4*>(H + (size_t)i * 80 + lane * 4);
            acc.x = fmaf(w, v.x, acc.x); acc.y = fmaf(w, v.y, acc.y);
            acc.z = fmaf(w, v.z, acc.z); acc.w = fmaf(w, v.w, acc.w);
        }
    }
    const float inv = 1.0f / den;
    float4 v;                                  // normalized per-head values
    v.x = acc.x * inv; v.y = acc.y * inv; v.z = acc.z * inv; v.w = acc.w * inv;

    // head mean: lanes 0..9 pair with lanes 10..19
    float4 o;
    o.x = __shfl_sync(0xffffffffu, v.x, lane + 10);
    o.y = __shfl_sync(0xffffffffu, v.y, lane + 10);
    o.z = __shfl_sync(0xffffffffu, v.z, lane + 10);
    o.w = __shfl_sync(0xffffffffu, v.w, lane + 10);

    float4 m = make_float4(-1e30f, -1e30f, -1e30f, -1e30f);
    if (lane < 10) {
        const float4 bv = *reinterpret_cast<const float4*>(b2 + lane * 4);
        m.x = 0.5f * (v.x + o.x) + bv.x;
        m.y = 0.5f * (v.y + o.y) + bv.y;
        m.z = 0.5f * (v.z + o.z) + bv.z;
        m.w = 0.5f * (v.w + o.w) + bv.w;
    }
    float mm = fmaxf(fmaxf(m.x, m.y), fmaxf(m.z, m.w));
    #pragma unroll
    for (int off = 16; off > 0; off >>= 1)
        mm = fmaxf(mm, __shfl_xor_sync(0xffffffffu, mm, off));
    float ssum = 0.f;
    if (lane < 10)
        ssum = __expf(m.x - mm) + __expf(m.y - mm) + __expf(m.z - mm) + __expf(m.w - mm);
    #pragma unroll
    for (int off = 16; off > 0; off >>= 1)
        ssum += __shfl_xor_sync(0xffffffffu, ssum, off);
    const float lse = mm + __logf(ssum);

    if (lane < 10) {
        float4 r;
        r.x = m.x - lse; r.y = m.y - lse; r.z = m.z - lse; r.w = m.w - lse;
        *reinterpret_cast<float4*>(out + (size_t)i * 40 + lane * 4) = r;
    }
}

// ------------------------------- launcher -------------------------------
extern "C" void kernel_launch(void* const* d_in, const int* in_sizes, int n_in,
                              void* d_out, int out_size)
{
    const float* x      = (const float*)d_in[0];
    const int*   ei     = (const int*)  d_in[1];
    const float* W1     = (const float*)d_in[2];
    const float* att_s1 = (const float*)d_in[3];
    const float* att_d1 = (const float*)d_in[4];
    const float* b1     = (const float*)d_in[5];
    const float* gamma  = (const float*)d_in[6];
    const float* beta   = (const float*)d_in[7];
    const float* W2     = (const float*)d_in[8];
    const float* att_s2 = (const float*)d_in[9];
    const float* att_d2 = (const float*)d_in[10];
    const float* b2     = (const float*)d_in[11];
    float* out = (float*)d_out;

    const int n = in_sizes[0] / 128;
    const int E = in_sizes[1] / 2;
    const int* src = ei;
    const int* dst = ei + E;

    float *h1, *agg1, *h2, *colsum, *colsq, *scale, *shift;
    float2 *as1, *ad1, *as2, *ad2;
    int *deg, *incl, *rowptr, *cursor, *colarr, *bsum;
    cudaGetSymbolAddress((void**)&h1,     g_h1);
    cudaGetSymbolAddress((void**)&agg1,   g_agg1);
    cudaGetSymbolAddress((void**)&h2,     g_h2);
    cudaGetSymbolAddress((void**)&as1,    g_as1);
    cudaGetSymbolAddress((void**)&ad1,    g_ad1);
    cudaGetSymbolAddress((void**)&as2,    g_as2);
    cudaGetSymbolAddress((void**)&ad2,    g_ad2);
    cudaGetSymbolAddress((void**)&deg,    g_deg);
    cudaGetSymbolAddress((void**)&incl,   g_incl);
    cudaGetSymbolAddress((void**)&rowptr, g_rowptr);
    cudaGetSymbolAddress((void**)&cursor, g_cursor);
    cudaGetSymbolAddress((void**)&colarr, g_col);
    cudaGetSymbolAddress((void**)&bsum,   g_bsum);
    cudaGetSymbolAddress((void**)&colsum, g_colsum);
    cudaGetSymbolAddress((void**)&colsq,  g_colsq);
    cudaGetSymbolAddress((void**)&scale,  g_scale);
    cudaGetSymbolAddress((void**)&shift,  g_shift);

    const size_t smem1 = (128 * 128 + 64 * 132) * sizeof(float);  // 99328 B
    const size_t smem2 = (128 * 80  + 64 * 132) * sizeof(float);  // 74752 B
    cudaFuncSetAttribute((const void*)gemm_k<128>, cudaFuncAttributeMaxDynamicSharedMemorySize, (int)smem1);
    cudaFuncSetAttribute((const void*)gemm_k<80>,  cudaFuncAttributeMaxDynamicSharedMemorySize, (int)smem2);

    const int gb = (n + 63) / 64;         // gemm blocks
    const int wb = (n * 32 + 255) / 256;  // warp-per-node blocks
    const int nb = (n + 1023) / 1024;     // scan blocks

    // ---- CSR build (shared by both layers) ----
    zero_init_k<<<(n + 255) / 256, 256>>>(deg, colsum, colsq, n);
    hist_k<<<(E + 255) / 256, 256>>>(dst, deg, E);
    scan1_k<<<nb, 1024>>>(deg, incl, bsum, n);
    scan2_k<<<1, 32>>>(bsum, nb);
    scan3_k<<<(n + 255) / 256, 256>>>(incl, bsum, deg, rowptr, cursor, n);
    fill_k<<<(E + 255) / 256, 256>>>(src, dst, cursor, colarr, E);

    // ---- layer 1 ----
    gemm_k<128><<<gb, 256, smem1>>>(x, W1, h1, n, nullptr, nullptr,
                                    att_s1, att_d1, as1, ad1);
    gather1_k<<<wb, 256>>>(rowptr, colarr, as1, ad1, h1, b1, agg1, n);

    // ---- batchnorm stats + fold ----
    bnstats_k<<<(n + 255) / 256, 128>>>(agg1, colsum, colsq, n);
    bnfold_k<<<1, 128>>>(colsum, colsq, gamma, beta, scale, shift, n);

    // ---- layer 2 (BN folded into GEMM A-load) ----
    gemm_k<80><<<gb, 256, smem2>>>(agg1, W2, h2, n, scale, shift,
                                   att_s2, att_d2, as2, ad2);
    gather2_k<<<wb, 256>>>(rowptr, colarr, as2, ad2, h2, b2, out, n);
}